// round 2
// baseline (speedup 1.0000x reference)
#include <cuda_runtime.h>
#include <math.h>

// Shapes (fixed by the problem)
#define TDIM 2048   // T == S
#define CDIM 512    // I == O == E == Ev
#define BB   2
#define NBH  16     // B*H
#define DK   64     // KEY_DIM == VALUE_DIM

// Scratch (allocation-free rule: __device__ globals)
__device__ float g_K[BB * CDIM * TDIM];
__device__ float g_V[BB * CDIM * TDIM];
__device__ float g_Q[BB * CDIM * TDIM];
__device__ float g_O[BB * CDIM * TDIM];

// ---------------------------------------------------------------------------
// Kernel 1: fused projection GEMMs.
// C[b,e,t] = sum_i W[e,i] * X[b,i,t], for (K,Wk,x), (V,Wv,x), (Q,Wq,y).
// blockIdx.z encodes (proj, batch). 128x128 tile, BK=16, 8x8 micro-tile.
// ---------------------------------------------------------------------------
__global__ void __launch_bounds__(256) proj_kernel(
    const float* __restrict__ Wk, const float* __restrict__ Wv,
    const float* __restrict__ Wq, const float* __restrict__ x,
    const float* __restrict__ y)
{
    __shared__ float Ws[16][132];   // [i][e]
    __shared__ float Xs[16][132];   // [i][t]

    int pid  = blockIdx.z;
    int proj = pid >> 1, b = pid & 1;
    const float* W = (proj == 0) ? Wk : (proj == 1) ? Wv : Wq;
    const float* X = ((proj == 2) ? y : x) + (size_t)b * CDIM * TDIM;
    float*       C = ((proj == 0) ? g_K : (proj == 1) ? g_V : g_Q)
                     + (size_t)b * CDIM * TDIM;

    int e0 = blockIdx.y * 128, t0 = blockIdx.x * 128;
    int tid = threadIdx.x, ty = tid >> 4, tx = tid & 15;

    float acc[8][8] = {};

    for (int i0 = 0; i0 < CDIM; i0 += 16) {
        // W tile: 128 e-rows x 16 i-cols -> transposed into Ws[i][e]
        #pragma unroll
        for (int q = 0; q < 2; q++) {
            int idx = tid * 2 + q, r = idx >> 2, c4 = idx & 3;
            float4 w = *(const float4*)&W[(size_t)(e0 + r) * CDIM + i0 + c4 * 4];
            Ws[c4 * 4 + 0][r] = w.x; Ws[c4 * 4 + 1][r] = w.y;
            Ws[c4 * 4 + 2][r] = w.z; Ws[c4 * 4 + 3][r] = w.w;
        }
        // X tile: 16 i-rows x 128 t-cols, coalesced float4
        #pragma unroll
        for (int q = 0; q < 2; q++) {
            int idx = q * 256 + tid, r = idx >> 5, c = idx & 31;
            *(float4*)&Xs[r][c * 4] =
                *(const float4*)&X[(size_t)(i0 + r) * TDIM + t0 + c * 4];
        }
        __syncthreads();

        #pragma unroll 8
        for (int kk = 0; kk < 16; kk++) {
            float a[8], bb[8];
            *(float4*)&a[0]  = *(float4*)&Ws[kk][ty * 8];
            *(float4*)&a[4]  = *(float4*)&Ws[kk][ty * 8 + 4];
            *(float4*)&bb[0] = *(float4*)&Xs[kk][tx * 8];
            *(float4*)&bb[4] = *(float4*)&Xs[kk][tx * 8 + 4];
            #pragma unroll
            for (int i = 0; i < 8; i++)
                #pragma unroll
                for (int j = 0; j < 8; j++)
                    acc[i][j] = fmaf(a[i], bb[j], acc[i][j]);
        }
        __syncthreads();
    }

    #pragma unroll
    for (int i = 0; i < 8; i++) {
        float* row = &C[(size_t)(e0 + ty * 8 + i) * TDIM + t0 + tx * 8];
        *(float4*)row       = make_float4(acc[i][0], acc[i][1], acc[i][2], acc[i][3]);
        *(float4*)(row + 4) = make_float4(acc[i][4], acc[i][5], acc[i][6], acc[i][7]);
    }
}

// ---------------------------------------------------------------------------
// Kernel 2: fused flash attention (softmax over the T/keys axis).
// One CTA per (bh, 128-wide s-block). Iterates 16 t-tiles of 128.
//   scores[t,s] = 0.125 * (sum_k K[k,t]*Q[k,s] + mask[t,s])
//   online softmax over t; Oacc[v,s] += V[v,t] * P[t,s]
// ---------------------------------------------------------------------------
#define ATTN_SMEM_FLOATS (3 * 64 * 132 + 128 * 132 + 3 * 128 + 16 * 128)
#define ATTN_SMEM_BYTES  (ATTN_SMEM_FLOATS * 4)

__global__ void __launch_bounds__(256) attn_kernel(const float* __restrict__ mask)
{
    extern __shared__ float sm[];
    float* Qs   = sm;                   // [64][132]  (k, s)
    float* Ks   = Qs + 64 * 132;        // [64][132]  (k, t)
    float* Vs   = Ks + 64 * 132;        // [64][132]  (v, t)
    float* Ps   = Vs + 64 * 132;        // [128][132] (t, s)
    float* m_sm = Ps + 128 * 132;       // [128] running max per s
    float* a_sm = m_sm + 128;           // [128] alpha per s
    float* l_sm = a_sm + 128;           // [128] running denom per s
    float* red  = l_sm + 128;           // [16][128] reduction scratch

    int bh = blockIdx.y;
    int s0 = blockIdx.x * 128;
    int tid = threadIdx.x;
    int ty = tid >> 4, tx = tid & 15;   // scores micro-tile: 8t x 8s
    int vy = tid >> 5, sx = tid & 31;   // AV micro-tile: 8v x 4s

    const float* Qg = g_Q + (size_t)bh * DK * TDIM;
    const float* Kg = g_K + (size_t)bh * DK * TDIM;
    const float* Vg = g_V + (size_t)bh * DK * TDIM;

    // Load Q tile once: 64 x 128
    #pragma unroll
    for (int q = 0; q < 8; q++) {
        int idx = q * 256 + tid, r = idx >> 5, c = idx & 31;
        *(float4*)&Qs[r * 132 + c * 4] =
            *(const float4*)&Qg[(size_t)r * TDIM + s0 + c * 4];
    }
    if (tid < 128) { m_sm[tid] = -1e30f; l_sm[tid] = 0.0f; }

    float Oacc[8][4] = {};

    for (int t0 = 0; t0 < TDIM; t0 += 128) {
        __syncthreads();   // protect Ks/Vs against prior-tile AV readers
        #pragma unroll
        for (int q = 0; q < 8; q++) {
            int idx = q * 256 + tid, r = idx >> 5, c = idx & 31;
            *(float4*)&Ks[r * 132 + c * 4] =
                *(const float4*)&Kg[(size_t)r * TDIM + t0 + c * 4];
            *(float4*)&Vs[r * 132 + c * 4] =
                *(const float4*)&Vg[(size_t)r * TDIM + t0 + c * 4];
        }
        __syncthreads();

        // ---- scores: 8x8 per thread over k=0..63
        float sc[8][8] = {};
        #pragma unroll 8
        for (int k = 0; k < DK; k++) {
            float a[8], bq[8];
            *(float4*)&a[0]  = *(float4*)&Ks[k * 132 + ty * 8];
            *(float4*)&a[4]  = *(float4*)&Ks[k * 132 + ty * 8 + 4];
            *(float4*)&bq[0] = *(float4*)&Qs[k * 132 + tx * 8];
            *(float4*)&bq[4] = *(float4*)&Qs[k * 132 + tx * 8 + 4];
            #pragma unroll
            for (int i = 0; i < 8; i++)
                #pragma unroll
                for (int j = 0; j < 8; j++)
                    sc[i][j] = fmaf(a[i], bq[j], sc[i][j]);
        }

        // ---- mask + scale, per-thread column max
        float cmax[8];
        #pragma unroll
        for (int j = 0; j < 8; j++) cmax[j] = -1e30f;
        #pragma unroll
        for (int i = 0; i < 8; i++) {
            const float* mrow = mask + (size_t)(t0 + ty * 8 + i) * TDIM + s0 + tx * 8;
            float4 m0 = *(const float4*)mrow;
            float4 m1 = *(const float4*)(mrow + 4);
            float mv[8] = {m0.x, m0.y, m0.z, m0.w, m1.x, m1.y, m1.z, m1.w};
            #pragma unroll
            for (int j = 0; j < 8; j++) {
                sc[i][j] = (sc[i][j] + mv[j]) * 0.125f;
                cmax[j] = fmaxf(cmax[j], sc[i][j]);
            }
        }
        #pragma unroll
        for (int j = 0; j < 8; j++) red[ty * 128 + tx * 8 + j] = cmax[j];
        __syncthreads();

        // ---- column-wise running-max update (one thread per s)
        if (tid < 128) {
            float v = -1e30f;
            #pragma unroll
            for (int r = 0; r < 16; r++) v = fmaxf(v, red[r * 128 + tid]);
            float mo = m_sm[tid];
            float mn = fmaxf(mo, v);
            float al = __expf(mo - mn);
            m_sm[tid] = mn; a_sm[tid] = al; l_sm[tid] *= al;
        }
        __syncthreads();

        // ---- exponentiate, write P tile, accumulate column sums
        float mn[8];
        #pragma unroll
        for (int j = 0; j < 8; j++) mn[j] = m_sm[tx * 8 + j];
        float csum[8] = {};
        #pragma unroll
        for (int i = 0; i < 8; i++) {
            float p[8];
            #pragma unroll
            for (int j = 0; j < 8; j++) {
                p[j] = __expf(sc[i][j] - mn[j]);
                csum[j] += p[j];
            }
            float* prow = &Ps[(ty * 8 + i) * 132 + tx * 8];
            *(float4*)prow       = make_float4(p[0], p[1], p[2], p[3]);
            *(float4*)(prow + 4) = make_float4(p[4], p[5], p[6], p[7]);
        }
        #pragma unroll
        for (int j = 0; j < 8; j++) red[ty * 128 + tx * 8 + j] = csum[j];

        // rescale O accumulator by alpha for this tile (a_sm synced above)
        float alv[4];
        #pragma unroll
        for (int c = 0; c < 4; c++) alv[c] = a_sm[sx * 4 + c];
        #pragma unroll
        for (int i = 0; i < 8; i++)
            #pragma unroll
            for (int c = 0; c < 4; c++) Oacc[i][c] *= alv[c];
        __syncthreads();

        if (tid < 128) {
            float ssum = 0.0f;
            #pragma unroll
            for (int r = 0; r < 16; r++) ssum += red[r * 128 + tid];
            l_sm[tid] += ssum;
        }

        // ---- O[v,s] += sum_t V[v,t] * P[t,s]   (8v x 4s per thread)
        #pragma unroll 4
        for (int t = 0; t < 128; t++) {
            float4 pv = *(const float4*)&Ps[t * 132 + sx * 4];
            #pragma unroll
            for (int i = 0; i < 8; i++) {
                float v = Vs[(vy * 8 + i) * 132 + t];
                Oacc[i][0] = fmaf(v, pv.x, Oacc[i][0]);
                Oacc[i][1] = fmaf(v, pv.y, Oacc[i][1]);
                Oacc[i][2] = fmaf(v, pv.z, Oacc[i][2]);
                Oacc[i][3] = fmaf(v, pv.w, Oacc[i][3]);
            }
        }
    }
    __syncthreads();

    // ---- finalize: divide by denominator, store
    float linv[4];
    #pragma unroll
    for (int c = 0; c < 4; c++) linv[c] = 1.0f / l_sm[sx * 4 + c];
    float* Og = g_O + (size_t)bh * DK * TDIM;
    #pragma unroll
    for (int i = 0; i < 8; i++) {
        float4 v = make_float4(Oacc[i][0] * linv[0], Oacc[i][1] * linv[1],
                               Oacc[i][2] * linv[2], Oacc[i][3] * linv[3]);
        *(float4*)&Og[(size_t)(vy * 8 + i) * TDIM + s0 + sx * 4] = v;
    }
}

// ---------------------------------------------------------------------------
// Kernel 3: final linear. out[b,s,o] = sum_c O[b,c,s] * W[o,c] + bias[o]
// ---------------------------------------------------------------------------
__global__ void __launch_bounds__(256) final_kernel(
    const float* __restrict__ W, const float* __restrict__ bias,
    float* __restrict__ out)
{
    __shared__ float Ws[16][132];   // [c][o]
    __shared__ float As[16][132];   // [c][s]

    int b = blockIdx.z;
    const float* Ob = g_O + (size_t)b * CDIM * TDIM;
    int o0 = blockIdx.x * 128, s0 = blockIdx.y * 128;
    int tid = threadIdx.x, ty = tid >> 4, tx = tid & 15;  // ty: s, tx: o

    float acc[8][8] = {};

    for (int c0 = 0; c0 < CDIM; c0 += 16) {
        #pragma unroll
        for (int q = 0; q < 2; q++) {
            int idx = tid * 2 + q, r = idx >> 2, c4 = idx & 3;
            float4 w = *(const float4*)&W[(size_t)(o0 + r) * CDIM + c0 + c4 * 4];
            Ws[c4 * 4 + 0][r] = w.x; Ws[c4 * 4 + 1][r] = w.y;
            Ws[c4 * 4 + 2][r] = w.z; Ws[c4 * 4 + 3][r] = w.w;
        }
        #pragma unroll
        for (int q = 0; q < 2; q++) {
            int idx = q * 256 + tid, r = idx >> 5, c = idx & 31;
            *(float4*)&As[r][c * 4] =
                *(const float4*)&Ob[(size_t)(c0 + r) * TDIM + s0 + c * 4];
        }
        __syncthreads();

        #pragma unroll 8
        for (int kk = 0; kk < 16; kk++) {
            float a[8], bb[8];
            *(float4*)&a[0]  = *(float4*)&As[kk][ty * 8];
            *(float4*)&a[4]  = *(float4*)&As[kk][ty * 8 + 4];
            *(float4*)&bb[0] = *(float4*)&Ws[kk][tx * 8];
            *(float4*)&bb[4] = *(float4*)&Ws[kk][tx * 8 + 4];
            #pragma unroll
            for (int i = 0; i < 8; i++)
                #pragma unroll
                for (int j = 0; j < 8; j++)
                    acc[i][j] = fmaf(a[i], bb[j], acc[i][j]);
        }
        __syncthreads();
    }

    float bv[8];
    *(float4*)&bv[0] = *(const float4*)&bias[o0 + tx * 8];
    *(float4*)&bv[4] = *(const float4*)&bias[o0 + tx * 8 + 4];
    #pragma unroll
    for (int i = 0; i < 8; i++) {
        float* row = &out[((size_t)b * TDIM + s0 + ty * 8 + i) * CDIM + o0 + tx * 8];
        *(float4*)row       = make_float4(acc[i][0] + bv[0], acc[i][1] + bv[1],
                                          acc[i][2] + bv[2], acc[i][3] + bv[3]);
        *(float4*)(row + 4) = make_float4(acc[i][4] + bv[4], acc[i][5] + bv[5],
                                          acc[i][6] + bv[6], acc[i][7] + bv[7]);
    }
}

// ---------------------------------------------------------------------------
extern "C" void kernel_launch(void* const* d_in, const int* in_sizes, int n_in,
                              void* d_out, int out_size)
{
    const float* x    = (const float*)d_in[0];
    const float* y    = (const float*)d_in[1];
    const float* mask = (const float*)d_in[2];
    const float* Wk   = (const float*)d_in[3];
    const float* Wv   = (const float*)d_in[4];
    const float* Wq   = (const float*)d_in[5];
    const float* W    = (const float*)d_in[6];
    const float* bias = (const float*)d_in[7];
    float* out = (float*)d_out;

    cudaFuncSetAttribute(attn_kernel,
                         cudaFuncAttributeMaxDynamicSharedMemorySize,
                         ATTN_SMEM_BYTES);

    // 1) K,V,Q projections (proj x batch in grid.z)
    proj_kernel<<<dim3(16, 4, 6), 256>>>(Wk, Wv, Wq, x, y);
    // 2) fused flash attention: grid (s-tiles, bh)
    attn_kernel<<<dim3(16, NBH), 256, ATTN_SMEM_BYTES>>>(mask);
    // 3) output projection + bias
    final_kernel<<<dim3(4, 16, 2), 256>>>(W, bias, out);
}

// round 4
// speedup vs baseline: 1.2124x; 1.2124x over previous
#include <cuda_runtime.h>
#include <cuda_bf16.h>
#include <math.h>
#include <stdint.h>

// Shapes (fixed by the problem)
#define TDIM 2048   // T == S
#define CDIM 512    // I == O == E == Ev
#define BB   2
#define NBH  16     // B*H
#define DK   64     // KEY_DIM == VALUE_DIM

// Scratch (allocation-free rule: __device__ globals)
__device__ float g_K[BB * CDIM * TDIM];
__device__ float g_V[BB * CDIM * TDIM];
__device__ float g_Q[BB * CDIM * TDIM];
__device__ float g_O[BB * CDIM * TDIM];

// ============================================================================
// Warp-MMA helpers (baseline PTX: works on plain sm_103 target)
// ============================================================================
__device__ __forceinline__ uint32_t smem_u32(const void* p) {
    uint32_t a;
    asm("{ .reg .u64 t; cvta.to.shared.u64 t, %1; cvt.u32.u64 %0, t; }"
        : "=r"(a) : "l"(p));
    return a;
}
__device__ __forceinline__ void ldsm_x4(uint32_t addr, uint32_t* r) {
    asm volatile("ldmatrix.sync.aligned.m8n8.x4.shared.b16 {%0,%1,%2,%3}, [%4];"
                 : "=r"(r[0]), "=r"(r[1]), "=r"(r[2]), "=r"(r[3]) : "r"(addr));
}
__device__ __forceinline__ void ldsm_x4t(uint32_t addr, uint32_t* r) {
    asm volatile("ldmatrix.sync.aligned.m8n8.x4.trans.shared.b16 {%0,%1,%2,%3}, [%4];"
                 : "=r"(r[0]), "=r"(r[1]), "=r"(r[2]), "=r"(r[3]) : "r"(addr));
}
__device__ __forceinline__ void mma_bf16(float* d, const uint32_t* a,
                                         const uint32_t* b) {
    asm volatile(
        "mma.sync.aligned.m16n8k16.row.col.f32.bf16.bf16.f32 "
        "{%0,%1,%2,%3}, {%4,%5,%6,%7}, {%8,%9}, {%0,%1,%2,%3};"
        : "+f"(d[0]), "+f"(d[1]), "+f"(d[2]), "+f"(d[3])
        : "r"(a[0]), "r"(a[1]), "r"(a[2]), "r"(a[3]), "r"(b[0]), "r"(b[1]));
}

// fp32 -> bf16 hi/lo split of a float4, packed as bf16x2 pairs
__device__ __forceinline__ void cvt_split4(float4 v, uint2& hi, uint2& lo) {
    __nv_bfloat16 hx = __float2bfloat16(v.x), hy = __float2bfloat16(v.y),
                  hz = __float2bfloat16(v.z), hw = __float2bfloat16(v.w);
    __nv_bfloat16 lx = __float2bfloat16(v.x - __bfloat162float(hx));
    __nv_bfloat16 ly = __float2bfloat16(v.y - __bfloat162float(hy));
    __nv_bfloat16 lz = __float2bfloat16(v.z - __bfloat162float(hz));
    __nv_bfloat16 lw = __float2bfloat16(v.w - __bfloat162float(hw));
    hi.x = (uint32_t)__bfloat16_as_ushort(hx) | ((uint32_t)__bfloat16_as_ushort(hy) << 16);
    hi.y = (uint32_t)__bfloat16_as_ushort(hz) | ((uint32_t)__bfloat16_as_ushort(hw) << 16);
    lo.x = (uint32_t)__bfloat16_as_ushort(lx) | ((uint32_t)__bfloat16_as_ushort(ly) << 16);
    lo.y = (uint32_t)__bfloat16_as_ushort(lz) | ((uint32_t)__bfloat16_as_ushort(lw) << 16);
}

// ============================================================================
// Generic bf16x3 HMMA GEMM: D[128m x 128n] = A[m,k] * B[k,n]
//   A: row-major [m][k], stride CDIM.   B: row-major [k][n], stride TDIM.
// smem: A_hi[128][72 bf16] | A_lo | B_hi[64][136 bf16] | B_lo   (K staged 64)
// 8 warps; each warp owns 64m x 32n; micro: m16n8k16 bf16, fp32 accum.
// ============================================================================
#define A_STR_B 144            // 72 bf16 row stride (conflict-free ldmatrix)
#define B_STR_B 272            // 136 bf16 row stride
#define A_BYTES (128 * A_STR_B)       // 18432
#define B_BYTES (64 * B_STR_B)        // 17408
#define SM_ALO  A_BYTES
#define SM_BHI  (2 * A_BYTES)
#define SM_BLO  (2 * A_BYTES + B_BYTES)
#define GEMM_SMEM (2 * A_BYTES + 2 * B_BYTES)  // 71680 (>= 128*132*4 transpose buf)

__global__ void __launch_bounds__(256, 1) gemm_mma(
    const float* __restrict__ Wk, const float* __restrict__ Wv,
    const float* __restrict__ Wq, const float* __restrict__ x,
    const float* __restrict__ y,  const float* __restrict__ Wf,
    const float* __restrict__ bias, float* __restrict__ out, int zbase)
{
    extern __shared__ char smem[];
    uint32_t sb = smem_u32(smem);
    int tid = threadIdx.x, wid = tid >> 5, lane = tid & 31;

    int z = blockIdx.z + zbase;
    const float* Ag; const float* Bg;
    float* Cd = nullptr; float* Od = nullptr;
    if (z < 6) {
        int proj = z >> 1, b = z & 1;
        Ag = (proj == 0) ? Wk : (proj == 1) ? Wv : Wq;
        Bg = ((proj == 2) ? y : x) + (size_t)b * CDIM * TDIM;
        Cd = ((proj == 0) ? g_K : (proj == 1) ? g_V : g_Q) + (size_t)b * CDIM * TDIM;
    } else {
        int b = z - 6;
        Ag = Wf;
        Bg = g_O + (size_t)b * CDIM * TDIM;
        Od = out + (size_t)b * TDIM * CDIM;
    }
    int m0 = blockIdx.y * 128, n0 = blockIdx.x * 128;
    const float* At = Ag + (size_t)m0 * CDIM;
    const float* Bt = Bg + n0;

    int wm = (wid & 1) * 64;      // warp m-offset (2 warps along m)
    int wn = (wid >> 1) * 32;     // warp n-offset (4 warps along n)

    float d[4][4][4] = {};        // [mfrag][nfrag][regs]

    for (int k0 = 0; k0 < CDIM; k0 += 64) {
        __syncthreads();
        // ---- fill A: 128m x 64k
        #pragma unroll
        for (int q = 0; q < 8; q++) {
            int idx = q * 256 + tid;
            int r = idx >> 4, c4 = idx & 15;
            float4 w = *(const float4*)(At + (size_t)r * CDIM + k0 + c4 * 4);
            uint2 hi, lo; cvt_split4(w, hi, lo);
            uint32_t off = (uint32_t)(r * A_STR_B + c4 * 8);
            *(uint2*)(smem + off)          = hi;
            *(uint2*)(smem + SM_ALO + off) = lo;
        }
        // ---- fill B: 64k x 128n
        #pragma unroll
        for (int q = 0; q < 8; q++) {
            int idx = q * 256 + tid;
            int r = idx >> 5, c4 = idx & 31;
            float4 v = *(const float4*)(Bt + (size_t)(k0 + r) * TDIM + c4 * 4);
            uint2 hi, lo; cvt_split4(v, hi, lo);
            uint32_t off = (uint32_t)(r * B_STR_B + c4 * 8);
            *(uint2*)(smem + SM_BHI + off) = hi;
            *(uint2*)(smem + SM_BLO + off) = lo;
        }
        __syncthreads();

        #pragma unroll
        for (int kk = 0; kk < 4; kk++) {
            uint32_t ah[4][4], al[4][4];
            #pragma unroll
            for (int mf = 0; mf < 4; mf++) {
                uint32_t addr = sb
                    + (uint32_t)((wm + mf * 16 + (lane & 15)) * A_STR_B)
                    + (uint32_t)((kk * 16 + (lane >> 4) * 8) * 2);
                ldsm_x4(addr, ah[mf]);
                ldsm_x4(addr + A_BYTES, al[mf]);
            }
            #pragma unroll
            for (int nf2 = 0; nf2 < 2; nf2++) {
                uint32_t baddr = sb + SM_BHI
                    + (uint32_t)((kk * 16 + (lane & 15)) * B_STR_B)
                    + (uint32_t)((wn + nf2 * 16 + (lane >> 4) * 8) * 2);
                uint32_t bh[4], bl[4];
                ldsm_x4t(baddr, bh);
                ldsm_x4t(baddr + B_BYTES, bl);
                #pragma unroll
                for (int mf = 0; mf < 4; mf++) {
                    #pragma unroll
                    for (int h = 0; h < 2; h++) {
                        float* dd = d[mf][nf2 * 2 + h];
                        mma_bf16(dd, ah[mf], &bh[h * 2]);   // hi*hi
                        mma_bf16(dd, ah[mf], &bl[h * 2]);   // hi*lo
                        mma_bf16(dd, al[mf], &bh[h * 2]);   // lo*hi
                    }
                }
            }
        }
    }

    int g = lane >> 2, t = lane & 3;
    if (!Od) {
        // proj: C[m][n], row stride TDIM — store fragments directly
        #pragma unroll
        for (int mf = 0; mf < 4; mf++) {
            #pragma unroll
            for (int nf = 0; nf < 4; nf++) {
                float* p = Cd + (size_t)(m0 + wm + mf * 16 + g) * TDIM
                              + n0 + wn + nf * 8 + t * 2;
                p[0] = d[mf][nf][0];           p[1] = d[mf][nf][1];
                p[8 * TDIM] = d[mf][nf][2];    p[8 * TDIM + 1] = d[mf][nf][3];
            }
        }
    } else {
        // final: transpose via smem (reuse stage buffer), add bias,
        // store out[s][o] with s = n, o = m.
        __syncthreads();
        float* tr = (float*)smem;   // [n(128)][m pad 132]
        #pragma unroll
        for (int mf = 0; mf < 4; mf++) {
            #pragma unroll
            for (int nf = 0; nf < 4; nf++) {
                int mm = wm + mf * 16 + g;
                int nn = wn + nf * 8 + t * 2;
                tr[(nn + 0) * 132 + mm]     = d[mf][nf][0];
                tr[(nn + 1) * 132 + mm]     = d[mf][nf][1];
                tr[(nn + 0) * 132 + mm + 8] = d[mf][nf][2];
                tr[(nn + 1) * 132 + mm + 8] = d[mf][nf][3];
            }
        }
        __syncthreads();
        int rr = tid >> 1, hh = (tid & 1) * 64;
        float* drow = Od + (size_t)(n0 + rr) * CDIM + m0 + hh;
        const float* bv = bias + m0 + hh;
        #pragma unroll
        for (int j = 0; j < 16; j++) {
            float4 v = *(float4*)&tr[rr * 132 + hh + j * 4];
            v.x += bv[j*4+0]; v.y += bv[j*4+1]; v.z += bv[j*4+2]; v.w += bv[j*4+3];
            *(float4*)(drow + j * 4) = v;
        }
    }
}

// ---------------------------------------------------------------------------
// Kernel 2: fused flash attention (unchanged fp32 path from passing baseline)
// ---------------------------------------------------------------------------
#define ATTN_SMEM_FLOATS (3 * 64 * 132 + 128 * 132 + 3 * 128 + 16 * 128)
#define ATTN_SMEM_BYTES  (ATTN_SMEM_FLOATS * 4)

__global__ void __launch_bounds__(256) attn_kernel(const float* __restrict__ mask)
{
    extern __shared__ float sm[];
    float* Qs   = sm;
    float* Ks   = Qs + 64 * 132;
    float* Vs   = Ks + 64 * 132;
    float* Ps   = Vs + 64 * 132;
    float* m_sm = Ps + 128 * 132;
    float* a_sm = m_sm + 128;
    float* l_sm = a_sm + 128;
    float* red  = l_sm + 128;

    int bh = blockIdx.y;
    int s0 = blockIdx.x * 128;
    int tid = threadIdx.x;
    int ty = tid >> 4, tx = tid & 15;
    int vy = tid >> 5, sx = tid & 31;

    const float* Qg = g_Q + (size_t)bh * DK * TDIM;
    const float* Kg = g_K + (size_t)bh * DK * TDIM;
    const float* Vg = g_V + (size_t)bh * DK * TDIM;

    #pragma unroll
    for (int q = 0; q < 8; q++) {
        int idx = q * 256 + tid, r = idx >> 5, c = idx & 31;
        *(float4*)&Qs[r * 132 + c * 4] =
            *(const float4*)&Qg[(size_t)r * TDIM + s0 + c * 4];
    }
    if (tid < 128) { m_sm[tid] = -1e30f; l_sm[tid] = 0.0f; }

    float Oacc[8][4] = {};

    for (int t0 = 0; t0 < TDIM; t0 += 128) {
        __syncthreads();
        #pragma unroll
        for (int q = 0; q < 8; q++) {
            int idx = q * 256 + tid, r = idx >> 5, c = idx & 31;
            *(float4*)&Ks[r * 132 + c * 4] =
                *(const float4*)&Kg[(size_t)r * TDIM + t0 + c * 4];
            *(float4*)&Vs[r * 132 + c * 4] =
                *(const float4*)&Vg[(size_t)r * TDIM + t0 + c * 4];
        }
        __syncthreads();

        float sc[8][8] = {};
        #pragma unroll 8
        for (int k = 0; k < DK; k++) {
            float a[8], bq[8];
            *(float4*)&a[0]  = *(float4*)&Ks[k * 132 + ty * 8];
            *(float4*)&a[4]  = *(float4*)&Ks[k * 132 + ty * 8 + 4];
            *(float4*)&bq[0] = *(float4*)&Qs[k * 132 + tx * 8];
            *(float4*)&bq[4] = *(float4*)&Qs[k * 132 + tx * 8 + 4];
            #pragma unroll
            for (int i = 0; i < 8; i++)
                #pragma unroll
                for (int j = 0; j < 8; j++)
                    sc[i][j] = fmaf(a[i], bq[j], sc[i][j]);
        }

        float cmax[8];
        #pragma unroll
        for (int j = 0; j < 8; j++) cmax[j] = -1e30f;
        #pragma unroll
        for (int i = 0; i < 8; i++) {
            const float* mrow = mask + (size_t)(t0 + ty * 8 + i) * TDIM + s0 + tx * 8;
            float4 m0 = *(const float4*)mrow;
            float4 m1 = *(const float4*)(mrow + 4);
            float mv[8] = {m0.x, m0.y, m0.z, m0.w, m1.x, m1.y, m1.z, m1.w};
            #pragma unroll
            for (int j = 0; j < 8; j++) {
                sc[i][j] = (sc[i][j] + mv[j]) * 0.125f;
                cmax[j] = fmaxf(cmax[j], sc[i][j]);
            }
        }
        #pragma unroll
        for (int j = 0; j < 8; j++) red[ty * 128 + tx * 8 + j] = cmax[j];
        __syncthreads();

        if (tid < 128) {
            float v = -1e30f;
            #pragma unroll
            for (int r = 0; r < 16; r++) v = fmaxf(v, red[r * 128 + tid]);
            float mo = m_sm[tid];
            float mn = fmaxf(mo, v);
            float al = __expf(mo - mn);
            m_sm[tid] = mn; a_sm[tid] = al; l_sm[tid] *= al;
        }
        __syncthreads();

        float mn[8];
        #pragma unroll
        for (int j = 0; j < 8; j++) mn[j] = m_sm[tx * 8 + j];
        float csum[8] = {};
        #pragma unroll
        for (int i = 0; i < 8; i++) {
            float p[8];
            #pragma unroll
            for (int j = 0; j < 8; j++) {
                p[j] = __expf(sc[i][j] - mn[j]);
                csum[j] += p[j];
            }
            float* prow = &Ps[(ty * 8 + i) * 132 + tx * 8];
            *(float4*)prow       = make_float4(p[0], p[1], p[2], p[3]);
            *(float4*)(prow + 4) = make_float4(p[4], p[5], p[6], p[7]);
        }
        #pragma unroll
        for (int j = 0; j < 8; j++) red[ty * 128 + tx * 8 + j] = csum[j];

        float alv[4];
        #pragma unroll
        for (int c = 0; c < 4; c++) alv[c] = a_sm[sx * 4 + c];
        #pragma unroll
        for (int i = 0; i < 8; i++)
            #pragma unroll
            for (int c = 0; c < 4; c++) Oacc[i][c] *= alv[c];
        __syncthreads();

        if (tid < 128) {
            float ssum = 0.0f;
            #pragma unroll
            for (int r = 0; r < 16; r++) ssum += red[r * 128 + tid];
            l_sm[tid] += ssum;
        }

        #pragma unroll 4
        for (int t = 0; t < 128; t++) {
            float4 pv = *(const float4*)&Ps[t * 132 + sx * 4];
            #pragma unroll
            for (int i = 0; i < 8; i++) {
                float v = Vs[(vy * 8 + i) * 132 + t];
                Oacc[i][0] = fmaf(v, pv.x, Oacc[i][0]);
                Oacc[i][1] = fmaf(v, pv.y, Oacc[i][1]);
                Oacc[i][2] = fmaf(v, pv.z, Oacc[i][2]);
                Oacc[i][3] = fmaf(v, pv.w, Oacc[i][3]);
            }
        }
    }
    __syncthreads();

    float linv[4];
    #pragma unroll
    for (int c = 0; c < 4; c++) linv[c] = 1.0f / l_sm[sx * 4 + c];
    float* Og = g_O + (size_t)bh * DK * TDIM;
    #pragma unroll
    for (int i = 0; i < 8; i++) {
        float4 v = make_float4(Oacc[i][0] * linv[0], Oacc[i][1] * linv[1],
                               Oacc[i][2] * linv[2], Oacc[i][3] * linv[3]);
        *(float4*)&Og[(size_t)(vy * 8 + i) * TDIM + s0 + sx * 4] = v;
    }
}

// ---------------------------------------------------------------------------
extern "C" void kernel_launch(void* const* d_in, const int* in_sizes, int n_in,
                              void* d_out, int out_size)
{
    const float* x    = (const float*)d_in[0];
    const float* y    = (const float*)d_in[1];
    const float* mask = (const float*)d_in[2];
    const float* Wk   = (const float*)d_in[3];
    const float* Wv   = (const float*)d_in[4];
    const float* Wq   = (const float*)d_in[5];
    const float* W    = (const float*)d_in[6];
    const float* bias = (const float*)d_in[7];
    float* out = (float*)d_out;

    cudaFuncSetAttribute(gemm_mma, cudaFuncAttributeMaxDynamicSharedMemorySize,
                         GEMM_SMEM);
    cudaFuncSetAttribute(attn_kernel, cudaFuncAttributeMaxDynamicSharedMemorySize,
                         ATTN_SMEM_BYTES);

    // 1) K,V,Q projections: z = (proj, batch)
    gemm_mma<<<dim3(16, 4, 6), 256, GEMM_SMEM>>>(Wk, Wv, Wq, x, y, W, bias, out, 0);
    // 2) fused flash attention
    attn_kernel<<<dim3(16, NBH), 256, ATTN_SMEM_BYTES>>>(mask);
    // 3) output projection + bias (zbase=6 selects final mode)
    gemm_mma<<<dim3(16, 4, 2), 256, GEMM_SMEM>>>(Wk, Wv, Wq, x, y, W, bias, out, 6);
}

// round 5
// speedup vs baseline: 2.2507x; 1.8564x over previous
#include <cuda_runtime.h>
#include <cuda_bf16.h>
#include <math.h>
#include <stdint.h>

// Shapes (fixed by the problem)
#define TDIM 2048   // T == S
#define CDIM 512    // I == O == E == Ev
#define BB   2
#define NBH  16     // B*H
#define DK   64     // KEY_DIM == VALUE_DIM

// Scratch (allocation-free rule: __device__ globals)
__device__ float g_K[BB * CDIM * TDIM];
__device__ float g_V[BB * CDIM * TDIM];
__device__ float g_Q[BB * CDIM * TDIM];
__device__ float g_O[BB * CDIM * TDIM];

// ============================================================================
// Warp-MMA helpers (baseline PTX: works on plain sm_103 target)
// ============================================================================
__device__ __forceinline__ uint32_t smem_u32(const void* p) {
    uint32_t a;
    asm("{ .reg .u64 t; cvta.to.shared.u64 t, %1; cvt.u32.u64 %0, t; }"
        : "=r"(a) : "l"(p));
    return a;
}
__device__ __forceinline__ void ldsm_x4(uint32_t addr, uint32_t* r) {
    asm volatile("ldmatrix.sync.aligned.m8n8.x4.shared.b16 {%0,%1,%2,%3}, [%4];"
                 : "=r"(r[0]), "=r"(r[1]), "=r"(r[2]), "=r"(r[3]) : "r"(addr));
}
__device__ __forceinline__ void ldsm_x4t(uint32_t addr, uint32_t* r) {
    asm volatile("ldmatrix.sync.aligned.m8n8.x4.trans.shared.b16 {%0,%1,%2,%3}, [%4];"
                 : "=r"(r[0]), "=r"(r[1]), "=r"(r[2]), "=r"(r[3]) : "r"(addr));
}
__device__ __forceinline__ void mma_bf16(float* d, const uint32_t* a,
                                         const uint32_t* b) {
    asm volatile(
        "mma.sync.aligned.m16n8k16.row.col.f32.bf16.bf16.f32 "
        "{%0,%1,%2,%3}, {%4,%5,%6,%7}, {%8,%9}, {%0,%1,%2,%3};"
        : "+f"(d[0]), "+f"(d[1]), "+f"(d[2]), "+f"(d[3])
        : "r"(a[0]), "r"(a[1]), "r"(a[2]), "r"(a[3]), "r"(b[0]), "r"(b[1]));
}

// pack two fp32 -> bf16x2 (lo in low half), round-to-nearest
__device__ __forceinline__ uint32_t pack2(float lo, float hi) {
    uint32_t r;
    asm("cvt.rn.bf16x2.f32 %0, %1, %2;" : "=r"(r) : "f"(hi), "f"(lo));
    return r;
}
// fp32 -> bf16 hi/lo split of a float4, packed as bf16x2 pairs
__device__ __forceinline__ void split4(float4 v, uint2& hi, uint2& lo) {
    hi.x = pack2(v.x, v.y);
    hi.y = pack2(v.z, v.w);
    float hx = __int_as_float(hi.x << 16);
    float hy = __int_as_float(hi.x & 0xffff0000u);
    float hz = __int_as_float(hi.y << 16);
    float hw = __int_as_float(hi.y & 0xffff0000u);
    lo.x = pack2(v.x - hx, v.y - hy);
    lo.y = pack2(v.z - hz, v.w - hw);
}

// FMA-pipe exp (exp2 magic-number + degree-5 poly), rel err ~3e-7, x <= 0 ok
__device__ __forceinline__ float fexp(float x) {
    x = fmaxf(x, -87.0f);
    float y = fmaf(x, 1.44269504f, 12582912.0f);
    int   n = __float_as_int(y) - 0x4B400000;
    float nf = y - 12582912.0f;
    float f = fmaf(x, 1.44269504f, -nf);
    float p = 1.3390776e-3f;
    p = fmaf(p, f, 9.6181265e-3f);
    p = fmaf(p, f, 5.5504873e-2f);
    p = fmaf(p, f, 2.4022649e-1f);
    p = fmaf(p, f, 6.9314718e-1f);
    p = fmaf(p, f, 1.0f);
    return __int_as_float(__float_as_int(p) + (n << 23));
}

// ============================================================================
// Generic bf16x3 HMMA GEMM (unchanged from passing R4): D[128 x 128]
// ============================================================================
#define A_STR_B 144
#define B_STR_B 272
#define A_BYTES (128 * A_STR_B)
#define B_BYTES (64 * B_STR_B)
#define SM_ALO  A_BYTES
#define SM_BHI  (2 * A_BYTES)
#define SM_BLO  (2 * A_BYTES + B_BYTES)
#define GEMM_SMEM (2 * A_BYTES + 2 * B_BYTES)

__global__ void __launch_bounds__(256, 1) gemm_mma(
    const float* __restrict__ Wk, const float* __restrict__ Wv,
    const float* __restrict__ Wq, const float* __restrict__ x,
    const float* __restrict__ y,  const float* __restrict__ Wf,
    const float* __restrict__ bias, float* __restrict__ out, int zbase)
{
    extern __shared__ char smem[];
    uint32_t sb = smem_u32(smem);
    int tid = threadIdx.x, wid = tid >> 5, lane = tid & 31;

    int z = blockIdx.z + zbase;
    const float* Ag; const float* Bg;
    float* Cd = nullptr; float* Od = nullptr;
    if (z < 6) {
        int proj = z >> 1, b = z & 1;
        Ag = (proj == 0) ? Wk : (proj == 1) ? Wv : Wq;
        Bg = ((proj == 2) ? y : x) + (size_t)b * CDIM * TDIM;
        Cd = ((proj == 0) ? g_K : (proj == 1) ? g_V : g_Q) + (size_t)b * CDIM * TDIM;
    } else {
        int b = z - 6;
        Ag = Wf;
        Bg = g_O + (size_t)b * CDIM * TDIM;
        Od = out + (size_t)b * TDIM * CDIM;
    }
    int m0 = blockIdx.y * 128, n0 = blockIdx.x * 128;
    const float* At = Ag + (size_t)m0 * CDIM;
    const float* Bt = Bg + n0;

    int wm = (wid & 1) * 64;
    int wn = (wid >> 1) * 32;

    float d[4][4][4] = {};

    for (int k0 = 0; k0 < CDIM; k0 += 64) {
        __syncthreads();
        #pragma unroll
        for (int q = 0; q < 8; q++) {
            int idx = q * 256 + tid;
            int r = idx >> 4, c4 = idx & 15;
            float4 w = *(const float4*)(At + (size_t)r * CDIM + k0 + c4 * 4);
            uint2 hi, lo; split4(w, hi, lo);
            uint32_t off = (uint32_t)(r * A_STR_B + c4 * 8);
            *(uint2*)(smem + off)          = hi;
            *(uint2*)(smem + SM_ALO + off) = lo;
        }
        #pragma unroll
        for (int q = 0; q < 8; q++) {
            int idx = q * 256 + tid;
            int r = idx >> 5, c4 = idx & 31;
            float4 v = *(const float4*)(Bt + (size_t)(k0 + r) * TDIM + c4 * 4);
            uint2 hi, lo; split4(v, hi, lo);
            uint32_t off = (uint32_t)(r * B_STR_B + c4 * 8);
            *(uint2*)(smem + SM_BHI + off) = hi;
            *(uint2*)(smem + SM_BLO + off) = lo;
        }
        __syncthreads();

        #pragma unroll
        for (int kk = 0; kk < 4; kk++) {
            uint32_t ah[4][4], al[4][4];
            #pragma unroll
            for (int mf = 0; mf < 4; mf++) {
                uint32_t addr = sb
                    + (uint32_t)((wm + mf * 16 + (lane & 15)) * A_STR_B)
                    + (uint32_t)((kk * 16 + (lane >> 4) * 8) * 2);
                ldsm_x4(addr, ah[mf]);
                ldsm_x4(addr + A_BYTES, al[mf]);
            }
            #pragma unroll
            for (int nf2 = 0; nf2 < 2; nf2++) {
                uint32_t baddr = sb + SM_BHI
                    + (uint32_t)((kk * 16 + (lane & 15)) * B_STR_B)
                    + (uint32_t)((wn + nf2 * 16 + (lane >> 4) * 8) * 2);
                uint32_t bh[4], bl[4];
                ldsm_x4t(baddr, bh);
                ldsm_x4t(baddr + B_BYTES, bl);
                #pragma unroll
                for (int mf = 0; mf < 4; mf++) {
                    #pragma unroll
                    for (int h = 0; h < 2; h++) {
                        float* dd = d[mf][nf2 * 2 + h];
                        mma_bf16(dd, ah[mf], &bh[h * 2]);
                        mma_bf16(dd, ah[mf], &bl[h * 2]);
                        mma_bf16(dd, al[mf], &bh[h * 2]);
                    }
                }
            }
        }
    }

    int g = lane >> 2, t = lane & 3;
    if (!Od) {
        #pragma unroll
        for (int mf = 0; mf < 4; mf++) {
            #pragma unroll
            for (int nf = 0; nf < 4; nf++) {
                float* p = Cd + (size_t)(m0 + wm + mf * 16 + g) * TDIM
                              + n0 + wn + nf * 8 + t * 2;
                p[0] = d[mf][nf][0];           p[1] = d[mf][nf][1];
                p[8 * TDIM] = d[mf][nf][2];    p[8 * TDIM + 1] = d[mf][nf][3];
            }
        }
    } else {
        __syncthreads();
        float* tr = (float*)smem;
        #pragma unroll
        for (int mf = 0; mf < 4; mf++) {
            #pragma unroll
            for (int nf = 0; nf < 4; nf++) {
                int mm = wm + mf * 16 + g;
                int nn = wn + nf * 8 + t * 2;
                tr[(nn + 0) * 132 + mm]     = d[mf][nf][0];
                tr[(nn + 1) * 132 + mm]     = d[mf][nf][1];
                tr[(nn + 0) * 132 + mm + 8] = d[mf][nf][2];
                tr[(nn + 1) * 132 + mm + 8] = d[mf][nf][3];
            }
        }
        __syncthreads();
        int rr = tid >> 1, hh = (tid & 1) * 64;
        float* drow = Od + (size_t)(n0 + rr) * CDIM + m0 + hh;
        const float* bv = bias + m0 + hh;
        #pragma unroll
        for (int j = 0; j < 16; j++) {
            float4 v = *(float4*)&tr[rr * 132 + hh + j * 4];
            v.x += bv[j*4+0]; v.y += bv[j*4+1]; v.z += bv[j*4+2]; v.w += bv[j*4+3];
            *(float4*)(drow + j * 4) = v;
        }
    }
}

// ============================================================================
// HMMA flash attention: per CTA one (bh, 128-s block), 16 t-tiles of 128.
// All tiles [64 rows][128 cols] bf16, padded to 136 bf16 (272 B) per row.
// ============================================================================
#define STR 272
#define SM_QH 0
#define SM_QL 17408
#define SM_KH 34816
#define SM_KL 52224
#define SM_VH 69632
#define SM_VL 87040
#define SM_PH 104448
#define SM_PL 139264
#define SM_M  174080
#define SM_A  174592
#define SM_L  175104
#define SM_RED 175616
#define ATTN_SMEM 176640

__global__ void __launch_bounds__(256, 1) attn_mma(const float* __restrict__ mask)
{
    extern __shared__ char smem[];
    uint32_t sb = smem_u32(smem);
    float* m_sm = (float*)(smem + SM_M);
    float* a_sm = (float*)(smem + SM_A);
    float* l_sm = (float*)(smem + SM_L);
    float* red  = (float*)(smem + SM_RED);

    int tid = threadIdx.x, wid = tid >> 5, lane = tid & 31;
    int g = lane >> 2, t2 = lane & 3;
    int bh = blockIdx.y, s0 = blockIdx.x * 128;
    int wmt = (wid & 1) * 64;    // t offset (scores)
    int wmv = (wid & 1) * 32;    // v offset (PV)
    int ws  = (wid >> 1) * 32;   // s offset (both)

    const float* Qg = g_Q + (size_t)bh * DK * TDIM + s0;
    const float* Kg = g_K + (size_t)bh * DK * TDIM;
    const float* Vg = g_V + (size_t)bh * DK * TDIM;

    // Q fill (once): [k=64][s=128] hi/lo
    #pragma unroll
    for (int q = 0; q < 8; q++) {
        int idx = q * 256 + tid, r = idx >> 5, c4 = idx & 31;
        float4 v = *(const float4*)(Qg + (size_t)r * TDIM + c4 * 4);
        uint2 hi, lo; split4(v, hi, lo);
        *(uint2*)(smem + SM_QH + r * STR + c4 * 8) = hi;
        *(uint2*)(smem + SM_QL + r * STR + c4 * 8) = lo;
    }
    if (tid < 128) { m_sm[tid] = -1e30f; l_sm[tid] = 0.0f; }

    float o[2][4][4] = {};

    for (int t0 = 0; t0 < TDIM; t0 += 128) {
        __syncthreads();   // prev PV done reading V/P; red/l settled
        #pragma unroll
        for (int q = 0; q < 8; q++) {
            int idx = q * 256 + tid, r = idx >> 5, c4 = idx & 31;
            float4 kv = *(const float4*)(Kg + (size_t)r * TDIM + t0 + c4 * 4);
            uint2 hi, lo; split4(kv, hi, lo);
            *(uint2*)(smem + SM_KH + r * STR + c4 * 8) = hi;
            *(uint2*)(smem + SM_KL + r * STR + c4 * 8) = lo;
            float4 vv = *(const float4*)(Vg + (size_t)r * TDIM + t0 + c4 * 4);
            split4(vv, hi, lo);
            *(uint2*)(smem + SM_VH + r * STR + c4 * 8) = hi;
            *(uint2*)(smem + SM_VL + r * STR + c4 * 8) = lo;
        }
        __syncthreads();

        // ---- scores: S[t][s] = K^T Q, bf16x3. A from K [k][t] via trans
        // ldmatrix with custom lane->matrix map (a0..a3 in canonical order).
        float sc[4][4][4] = {};
        #pragma unroll
        for (int kk = 0; kk < 4; kk++) {
            uint32_t ah[4][4], al[4][4];
            #pragma unroll
            for (int mf = 0; mf < 4; mf++) {
                uint32_t ar = sb
                    + (uint32_t)((kk * 16 + (lane & 7) + ((lane >> 4) << 3)) * STR)
                    + (uint32_t)((wmt + mf * 16 + (((lane >> 3) & 1) << 3)) * 2);
                ldsm_x4t(ar + SM_KH, ah[mf]);
                ldsm_x4t(ar + SM_KL, al[mf]);
            }
            #pragma unroll
            for (int nf2 = 0; nf2 < 2; nf2++) {
                uint32_t br = sb
                    + (uint32_t)((kk * 16 + (lane & 15)) * STR)
                    + (uint32_t)((ws + nf2 * 16 + ((lane >> 4) << 3)) * 2);
                uint32_t bh4[4], bl4[4];
                ldsm_x4t(br + SM_QH, bh4);
                ldsm_x4t(br + SM_QL, bl4);
                #pragma unroll
                for (int mf = 0; mf < 4; mf++) {
                    #pragma unroll
                    for (int h = 0; h < 2; h++) {
                        float* dd = sc[mf][nf2 * 2 + h];
                        mma_bf16(dd, ah[mf], &bh4[h * 2]);
                        mma_bf16(dd, ah[mf], &bl4[h * 2]);
                        mma_bf16(dd, al[mf], &bh4[h * 2]);
                    }
                }
            }
        }

        // ---- mask + scale, per-col (s) max over this tile
        float cmax[8];
        #pragma unroll
        for (int j = 0; j < 8; j++) cmax[j] = -1e30f;
        #pragma unroll
        for (int mf = 0; mf < 4; mf++) {
            #pragma unroll
            for (int j2 = 0; j2 < 2; j2++) {
                int t = t0 + wmt + mf * 16 + g + j2 * 8;
                const float* mrow = mask + (size_t)t * TDIM + s0 + ws;
                #pragma unroll
                for (int nf = 0; nf < 4; nf++) {
                    float2 mk = *(const float2*)(mrow + nf * 8 + t2 * 2);
                    float a0 = (sc[mf][nf][j2 * 2 + 0] + mk.x) * 0.125f;
                    float a1 = (sc[mf][nf][j2 * 2 + 1] + mk.y) * 0.125f;
                    sc[mf][nf][j2 * 2 + 0] = a0;
                    sc[mf][nf][j2 * 2 + 1] = a1;
                    cmax[nf * 2 + 0] = fmaxf(cmax[nf * 2 + 0], a0);
                    cmax[nf * 2 + 1] = fmaxf(cmax[nf * 2 + 1], a1);
                }
            }
        }
        #pragma unroll
        for (int j = 0; j < 8; j++) {
            cmax[j] = fmaxf(cmax[j], __shfl_xor_sync(0xffffffffu, cmax[j], 4));
            cmax[j] = fmaxf(cmax[j], __shfl_xor_sync(0xffffffffu, cmax[j], 8));
            cmax[j] = fmaxf(cmax[j], __shfl_xor_sync(0xffffffffu, cmax[j], 16));
        }
        if (g == 0) {
            #pragma unroll
            for (int nf = 0; nf < 4; nf++) {
                red[(wid & 1) * 128 + ws + nf * 8 + t2 * 2 + 0] = cmax[nf * 2 + 0];
                red[(wid & 1) * 128 + ws + nf * 8 + t2 * 2 + 1] = cmax[nf * 2 + 1];
            }
        }
        __syncthreads();
        if (tid < 128) {
            float mt = fmaxf(red[tid], red[128 + tid]);
            float mo = m_sm[tid];
            float mn = fmaxf(mo, mt);
            float al = fexp(mo - mn);
            m_sm[tid] = mn; a_sm[tid] = al; l_sm[tid] *= al;
        }
        __syncthreads();

        // ---- alpha rescale O, exp (FMA pipe), P hi/lo -> smem, col sums
        float mcol[8], acol[8];
        #pragma unroll
        for (int nf = 0; nf < 4; nf++) {
            int sl = ws + nf * 8 + t2 * 2;
            mcol[nf * 2 + 0] = m_sm[sl];     mcol[nf * 2 + 1] = m_sm[sl + 1];
            acol[nf * 2 + 0] = a_sm[sl];     acol[nf * 2 + 1] = a_sm[sl + 1];
        }
        #pragma unroll
        for (int mf = 0; mf < 2; mf++) {
            #pragma unroll
            for (int nf = 0; nf < 4; nf++) {
                o[mf][nf][0] *= acol[nf * 2];     o[mf][nf][1] *= acol[nf * 2 + 1];
                o[mf][nf][2] *= acol[nf * 2];     o[mf][nf][3] *= acol[nf * 2 + 1];
            }
        }
        float csum[8];
        #pragma unroll
        for (int j = 0; j < 8; j++) csum[j] = 0.0f;
        #pragma unroll
        for (int mf = 0; mf < 4; mf++) {
            #pragma unroll
            for (int j2 = 0; j2 < 2; j2++) {
                int tl = wmt + mf * 16 + g + j2 * 8;
                #pragma unroll
                for (int nf = 0; nf < 4; nf++) {
                    float e0 = fexp(sc[mf][nf][j2 * 2 + 0] - mcol[nf * 2 + 0]);
                    float e1 = fexp(sc[mf][nf][j2 * 2 + 1] - mcol[nf * 2 + 1]);
                    csum[nf * 2 + 0] += e0;
                    csum[nf * 2 + 1] += e1;
                    uint32_t ph = pack2(e0, e1);
                    float h0 = __int_as_float(ph << 16);
                    float h1 = __int_as_float(ph & 0xffff0000u);
                    uint32_t pl = pack2(e0 - h0, e1 - h1);
                    uint32_t off = (uint32_t)(tl * STR + (ws + nf * 8 + t2 * 2) * 2);
                    *(uint32_t*)(smem + SM_PH + off) = ph;
                    *(uint32_t*)(smem + SM_PL + off) = pl;
                }
            }
        }
        #pragma unroll
        for (int j = 0; j < 8; j++) {
            csum[j] += __shfl_xor_sync(0xffffffffu, csum[j], 4);
            csum[j] += __shfl_xor_sync(0xffffffffu, csum[j], 8);
            csum[j] += __shfl_xor_sync(0xffffffffu, csum[j], 16);
        }
        if (g == 0) {
            #pragma unroll
            for (int nf = 0; nf < 4; nf++) {
                red[(wid & 1) * 128 + ws + nf * 8 + t2 * 2 + 0] = csum[nf * 2 + 0];
                red[(wid & 1) * 128 + ws + nf * 8 + t2 * 2 + 1] = csum[nf * 2 + 1];
            }
        }
        __syncthreads();   // P visible; red(csum) visible
        if (tid < 128) l_sm[tid] += red[tid] + red[128 + tid];

        // ---- O[v][s] += V P, bf16x3 (A = V [v][t] standard, B = P trans)
        #pragma unroll
        for (int kt = 0; kt < 8; kt++) {
            uint32_t avh[2][4], avl[2][4];
            #pragma unroll
            for (int mf = 0; mf < 2; mf++) {
                uint32_t ar = sb
                    + (uint32_t)((wmv + mf * 16 + (lane & 15)) * STR)
                    + (uint32_t)((kt * 16 + ((lane >> 4) << 3)) * 2);
                ldsm_x4(ar + SM_VH, avh[mf]);
                ldsm_x4(ar + SM_VL, avl[mf]);
            }
            #pragma unroll
            for (int nf2 = 0; nf2 < 2; nf2++) {
                uint32_t br = sb
                    + (uint32_t)((kt * 16 + (lane & 15)) * STR)
                    + (uint32_t)((ws + nf2 * 16 + ((lane >> 4) << 3)) * 2);
                uint32_t bh4[4], bl4[4];
                ldsm_x4t(br + SM_PH, bh4);
                ldsm_x4t(br + SM_PL, bl4);
                #pragma unroll
                for (int mf = 0; mf < 2; mf++) {
                    #pragma unroll
                    for (int h = 0; h < 2; h++) {
                        float* dd = o[mf][nf2 * 2 + h];
                        mma_bf16(dd, avh[mf], &bh4[h * 2]);
                        mma_bf16(dd, avh[mf], &bl4[h * 2]);
                        mma_bf16(dd, avl[mf], &bh4[h * 2]);
                    }
                }
            }
        }
    }
    __syncthreads();

    // ---- finalize: O / l -> g_O[v][s]
    float* Og = g_O + (size_t)bh * DK * TDIM + s0;
    #pragma unroll
    for (int nf = 0; nf < 4; nf++) {
        int sl = ws + nf * 8 + t2 * 2;
        float i0 = 1.0f / l_sm[sl], i1 = 1.0f / l_sm[sl + 1];
        #pragma unroll
        for (int mf = 0; mf < 2; mf++) {
            #pragma unroll
            for (int j2 = 0; j2 < 2; j2++) {
                int v = wmv + mf * 16 + g + j2 * 8;
                float2 st = make_float2(o[mf][nf][j2 * 2 + 0] * i0,
                                        o[mf][nf][j2 * 2 + 1] * i1);
                *(float2*)(Og + (size_t)v * TDIM + sl) = st;
            }
        }
    }
}

// ---------------------------------------------------------------------------
extern "C" void kernel_launch(void* const* d_in, const int* in_sizes, int n_in,
                              void* d_out, int out_size)
{
    const float* x    = (const float*)d_in[0];
    const float* y    = (const float*)d_in[1];
    const float* mask = (const float*)d_in[2];
    const float* Wk   = (const float*)d_in[3];
    const float* Wv   = (const float*)d_in[4];
    const float* Wq   = (const float*)d_in[5];
    const float* W    = (const float*)d_in[6];
    const float* bias = (const float*)d_in[7];
    float* out = (float*)d_out;

    cudaFuncSetAttribute(gemm_mma, cudaFuncAttributeMaxDynamicSharedMemorySize,
                         GEMM_SMEM);
    cudaFuncSetAttribute(attn_mma, cudaFuncAttributeMaxDynamicSharedMemorySize,
                         ATTN_SMEM);

    // 1) K,V,Q projections: z = (proj, batch)
    gemm_mma<<<dim3(16, 4, 6), 256, GEMM_SMEM>>>(Wk, Wv, Wq, x, y, W, bias, out, 0);
    // 2) HMMA flash attention: grid (s-blocks, bh)
    attn_mma<<<dim3(16, NBH), 256, ATTN_SMEM>>>(mask);
    // 3) output projection + bias (zbase=6 selects final mode)
    gemm_mma<<<dim3(16, 4, 2), 256, GEMM_SMEM>>>(Wk, Wv, Wq, x, y, W, bias, out, 6);
}